// round 3
// baseline (speedup 1.0000x reference)
#include <cuda_runtime.h>

// LinearSpline: per-channel slope-clipped linear spline activation, fused.
// x: [32, 64, 128, 128] f32, coefficients_vect: [64*51] f32, scaling: [64] f32.
//
// Single kernel. Each block serves one channel (channel constant across the
// block's contiguous element range), rebuilds that channel's 50-entry
// {value, slope} table in shared memory, then streams 512 float4s.

#define NCH   64
#define SZ    51
#define HALF  25                               // SIZE // 2
#define GRID_D   (2.0 * 1.0 / (SZ - 1))        // 0.04 (double, matches python)
#define GRID_F   ((float)GRID_D)
#define CLAMP_LO ((float)(-(GRID_D * HALF)))   // -1.0f
#define CLAMP_HI ((float)(GRID_D * (HALF - 1)))// 0.96f
#define INV_GRID (1.0f / GRID_F)               // folds to exactly 25.0f
#define FLOOR_EPS 1e-6f                        // fixes top-clamp floor (23.99999946 -> 24)

#define THREADS   256
#define V4_PER_T  2                            // float4s per thread
#define V4_PER_B  (THREADS * V4_PER_T)         // 512 float4 = 2048 elements per block

__global__ void __launch_bounds__(THREADS)
spline_fused_kernel(const float4* __restrict__ x,
                    const float*  __restrict__ coeff,
                    const float*  __restrict__ scale,
                    float4* __restrict__ out) {
    __shared__ float2 tab[SZ - 1];             // {c0, slope} per interval
    __shared__ float  sh_s[2];                 // {s, 1/s}

    int b = blockIdx.x;
    // block's first element index = b*512*4 = b*2048 ; channel = (elem>>14)&63
    int c = (b >> 3) & (NCH - 1);

    if (threadIdx.x == 0) {
        const float* cs = coeff + c * SZ;
        float vals[SZ];
        vals[0] = 0.0f;
        float acc = 0.0f;
        float prev = cs[0];
#pragma unroll
        for (int i = 1; i < SZ; ++i) {
            float cur = cs[i];
            float slope = fminf(fmaxf(cur - prev, 0.0f), GRID_F);
            acc += slope;
            vals[i] = acc;
            prev = cur;
        }
        float mid = vals[HALF];
#pragma unroll
        for (int j = 0; j < SZ - 1; ++j)
            tab[j] = make_float2(vals[j] - mid, vals[j + 1] - vals[j]);
        float s = scale[c];
        sh_s[0] = s;
        sh_s[1] = __fdividef(1.0f, s);
    }
    __syncthreads();

    float s     = sh_s[0];
    float inv_s = sh_s[1];
    int base = b * V4_PER_B + threadIdx.x;

    float4 vin[V4_PER_T];
#pragma unroll
    for (int u = 0; u < V4_PER_T; ++u)
        vin[u] = __ldcs(x + base + u * THREADS);

#pragma unroll
    for (int u = 0; u < V4_PER_T; ++u) {
        float xin[4] = {vin[u].x, vin[u].y, vin[u].z, vin[u].w};
        float r[4];
#pragma unroll
        for (int k = 0; k < 4; ++k) {
            float xs = xin[k] * s;
            float xc = fminf(fmaxf(xs, CLAMP_LO), CLAMP_HI);
            float fl = floorf(fmaf(xc, INV_GRID, FLOOR_EPS));   // [-25, 24]
            float fr = fmaf(xs, INV_GRID, -fl);                 // frac from UNCLAMPED xs
            int idx  = HALF + (int)fl;                          // [0, 49]
            float2 p = tab[idx];                                // LDS.64
            r[k] = fmaf(fr, p.y, p.x) * inv_s;
        }
        __stcs(out + base + u * THREADS, make_float4(r[0], r[1], r[2], r[3]));
    }
}

extern "C" void kernel_launch(void* const* d_in, const int* in_sizes, int n_in,
                              void* d_out, int out_size) {
    const float* x     = (const float*)d_in[0];
    const float* coeff = (const float*)d_in[1];
    const float* scl   = (const float*)d_in[2];
    float* out = (float*)d_out;

    int n  = out_size;                 // 33554432
    int n4 = n / 4;                    // 8388608 float4s
    int blocks = n4 / V4_PER_B;        // 16384 (exact: 8388608 / 512)
    spline_fused_kernel<<<blocks, THREADS>>>((const float4*)x, coeff, scl,
                                             (float4*)out);
}

// round 4
// speedup vs baseline: 1.2180x; 1.2180x over previous
#include <cuda_runtime.h>

// LinearSpline: per-channel slope-clipped linear spline activation, fused.
// x: [32, 64, 128, 128] f32, coefficients_vect: [64*51] f32, scaling: [64] f32.
//
// Single kernel. Channel is constant per block. Warp 0 rebuilds the channel's
// 50-entry {value, slope} table via a shfl parallel scan (no serial chain),
// then the block streams 512 float4s with shared-memory gathers.

#define NCH   64
#define SZ    51
#define HALF  25                               // SIZE // 2
#define GRID_D   (2.0 * 1.0 / (SZ - 1))        // 0.04 (double, matches python)
#define GRID_F   ((float)GRID_D)
#define CLAMP_LO ((float)(-(GRID_D * HALF)))   // -1.0f
#define CLAMP_HI ((float)(GRID_D * (HALF - 1)))// 0.96f
#define INV_GRID (1.0f / GRID_F)               // folds to exactly 25.0f
#define FLOOR_EPS 1e-6f                        // fixes top-clamp floor (23.99999946 -> 24)

#define THREADS   256
#define V4_PER_T  2                            // float4s per thread
#define V4_PER_B  (THREADS * V4_PER_T)         // 512 float4 = 2048 elements per block

__global__ void __launch_bounds__(THREADS)
spline_fused_kernel(const float4* __restrict__ x,
                    const float*  __restrict__ coeff,
                    const float*  __restrict__ scale,
                    float4* __restrict__ out) {
    __shared__ float2 tab[SZ - 1];             // {c0, slope} per interval
    __shared__ float  sh_s[2];                 // {s, 1/s}

    int b = blockIdx.x;
    // block's first element = b*2048 ; plane = 16384 elems ; c = (b>>3) & 63
    int c = (b >> 3) & (NCH - 1);

    // ---- parallel table build: warp 0 only, shfl scan, no serial chain ----
    if (threadIdx.x < 32) {
        int lane = threadIdx.x;
        const float* cs = coeff + c * SZ;
        float a  = (2 * lane     <= 50) ? __ldg(cs + 2 * lane)     : 0.0f; // cs[2l]
        float bb = (2 * lane + 1 <= 50) ? __ldg(cs + 2 * lane + 1) : 0.0f; // cs[2l+1]
        float a_next = __shfl_down_sync(0xffffffff, a, 1);                 // cs[2l+2]
        float s_even = fminf(fmaxf(bb - a,      0.0f), GRID_F);  // slope[2l]
        float s_odd  = fminf(fmaxf(a_next - bb, 0.0f), GRID_F);  // slope[2l+1]
        float p = (lane <= 24) ? (s_even + s_odd) : 0.0f;
        float P = p;                                             // inclusive scan
#pragma unroll
        for (int off = 1; off < 32; off <<= 1) {
            float t = __shfl_up_sync(0xffffffff, P, off);
            if (lane >= off) P += t;
        }
        float v_even = P - p;                  // vals[2l]  (exclusive)
        float v_odd  = v_even + s_even;        // vals[2l+1]
        float mid = __shfl_sync(0xffffffff, v_odd, 12);   // vals[25]
        if (lane <= 24) {
            tab[2 * lane]     = make_float2(v_even - mid, s_even);
            tab[2 * lane + 1] = make_float2(v_odd  - mid, s_odd);
        }
        if (lane == 0) {
            float s = __ldg(scale + c);
            sh_s[0] = s;
            sh_s[1] = __fdividef(1.0f, s);
        }
    }
    __syncthreads();

    float s     = sh_s[0];
    float inv_s = sh_s[1];
    int base = b * V4_PER_B + threadIdx.x;

    float4 vin[V4_PER_T];
#pragma unroll
    for (int u = 0; u < V4_PER_T; ++u)
        vin[u] = __ldcs(x + base + u * THREADS);

#pragma unroll
    for (int u = 0; u < V4_PER_T; ++u) {
        float xin[4] = {vin[u].x, vin[u].y, vin[u].z, vin[u].w};
        float r[4];
#pragma unroll
        for (int k = 0; k < 4; ++k) {
            float xs = xin[k] * s;
            float xc = fminf(fmaxf(xs, CLAMP_LO), CLAMP_HI);
            float fl = floorf(fmaf(xc, INV_GRID, FLOOR_EPS));   // [-25, 24]
            float fr = fmaf(xs, INV_GRID, -fl);                 // frac from UNCLAMPED xs
            int idx  = HALF + (int)fl;                          // [0, 49]
            float2 p = tab[idx];                                // LDS.64 gather
            r[k] = fmaf(fr, p.y, p.x) * inv_s;
        }
        __stcs(out + base + u * THREADS, make_float4(r[0], r[1], r[2], r[3]));
    }
}

extern "C" void kernel_launch(void* const* d_in, const int* in_sizes, int n_in,
                              void* d_out, int out_size) {
    const float* x     = (const float*)d_in[0];
    const float* coeff = (const float*)d_in[1];
    const float* scl   = (const float*)d_in[2];
    float* out = (float*)d_out;

    int n  = out_size;                 // 33554432
    int n4 = n / 4;                    // 8388608 float4s
    int blocks = n4 / V4_PER_B;        // 16384
    spline_fused_kernel<<<blocks, THREADS>>>((const float4*)x, coeff, scl,
                                             (float4*)out);
}